// round 1
// baseline (speedup 1.0000x reference)
#include <cuda_runtime.h>
#include <cuda_bf16.h>
#include <cstdint>

// Problem constants (fixed by the dataset)
#define B_DIM   16
#define N_DIM   50000
#define E_DIM   1600000
#define CLAMP_MIN_F (-10.0f)
#define CLAMP_MAX_F ( 10.0f)
#define EPS_F   (1e-6f)

// Transposed (N, B) scratch: each node's 16 batch values are contiguous (64B).
// 3 x 3.2MB = 9.6MB -> fully L2-resident.
__device__ float g_ET [N_DIM * B_DIM];   // E transposed
__device__ float g_OT [N_DIM * B_DIM];   // o_pre transposed
__device__ float g_ACC[N_DIM * B_DIM];   // accumulator, init to E + chem_influence

// ---------------------------------------------------------------------------
// Kernel A: transpose + init accumulator.
// tid = b*N + n (coalesced reads of the three (B,N) arrays),
// writes to (n*16 + b) — 64B-strided scattered writes, L2-absorbed.
// ---------------------------------------------------------------------------
__global__ void prep_kernel(const float* __restrict__ chem,
                            const float* __restrict__ E,
                            const float* __restrict__ o_pre)
{
    int tid = blockIdx.x * blockDim.x + threadIdx.x;
    if (tid >= B_DIM * N_DIM) return;
    int b = tid / N_DIM;
    int n = tid - b * N_DIM;
    float e = E[tid];
    float c = chem[tid];
    float o = o_pre[tid];
    int t = n * B_DIM + b;
    g_ET [t] = e;
    g_OT [t] = o;
    g_ACC[t] = e + c;            // fold chem_influence into the accumulator init
}

// ---------------------------------------------------------------------------
// Kernel B: edge scatter. 4 lanes per edge; each lane owns 4 batches (float4).
// Oj/En loads are 16B vectors inside the edge's contiguous 64B block.
// red.global.add.v4.f32 -> one REDG.128 per lane (no return, L2-side add).
// ---------------------------------------------------------------------------
__global__ void edge_kernel(const float* __restrict__ w,
                            const int*   __restrict__ src,
                            const int*   __restrict__ dst)
{
    int t = blockIdx.x * blockDim.x + threadIdx.x;
    if (t >= E_DIM * 4) return;
    int e = t >> 2;
    int q = t & 3;

    int  s  = __ldg(&src[e]);
    int  d  = __ldg(&dst[e]);
    float wv = __ldg(&w[e]);

    const float4 Oj = *reinterpret_cast<const float4*>(&g_OT[s * B_DIM + q * 4]);
    const float4 En = *reinterpret_cast<const float4*>(&g_ET[d * B_DIM + q * 4]);

    float4 c;
    c.x = (Oj.x >= En.x) ? (Oj.x * wv) : (-Oj.x * wv);
    c.y = (Oj.y >= En.y) ? (Oj.y * wv) : (-Oj.y * wv);
    c.z = (Oj.z >= En.z) ? (Oj.z * wv) : (-Oj.z * wv);
    c.w = (Oj.w >= En.w) ? (Oj.w * wv) : (-Oj.w * wv);

    float* p = &g_ACC[d * B_DIM + q * 4];
    asm volatile("red.global.add.v4.f32 [%0], {%1, %2, %3, %4};"
                 :: "l"(p), "f"(c.x), "f"(c.y), "f"(c.z), "f"(c.w)
                 : "memory");
}

// ---------------------------------------------------------------------------
// Kernel C: epilogue. tid = b*N + n so threshold/decay/E reads and the two
// output writes are coalesced; the g_ACC read is 64B-strided (L2 hit).
// ---------------------------------------------------------------------------
__global__ void final_kernel(const float* __restrict__ E,
                             const float* __restrict__ threshold,
                             const float* __restrict__ decay,
                             float* __restrict__ out)
{
    int tid = blockIdx.x * blockDim.x + threadIdx.x;
    if (tid >= B_DIM * N_DIM) return;
    int b = tid / N_DIM;
    int n = tid - b * N_DIM;

    float S = g_ACC[n * B_DIM + b];
    S = fminf(fmaxf(S, CLAMP_MIN_F), CLAMP_MAX_F);

    float thr = threshold[n];
    float dec = decay[n];
    float Ev  = E[tid];

    bool  gt    = S > thr;
    float new_o = fmaxf(S - thr, 0.0f);
    bool  mask  = (!gt) && (fabsf(S - Ev) <= EPS_F);
    float new_e = gt ? new_o : (mask ? (Ev - dec) : S);

    out[tid]                 = new_o;
    out[B_DIM * N_DIM + tid] = new_e;
}

// ---------------------------------------------------------------------------
// Launch. Inputs (metadata order):
//   0 chem_influence (B,N) f32   1 E (B,N) f32       2 o_pre (B,N) f32
//   3 w (E,) f32                 4 threshold (N,) f32 5 decay (N,) f32
//   6 src (E,) i32               7 dst (E,) i32
// Output: new_o (B,N) then new_e (B,N) concatenated, f32.
// ---------------------------------------------------------------------------
extern "C" void kernel_launch(void* const* d_in, const int* in_sizes, int n_in,
                              void* d_out, int out_size)
{
    const float* chem  = (const float*)d_in[0];
    const float* E     = (const float*)d_in[1];
    const float* o_pre = (const float*)d_in[2];
    const float* w     = (const float*)d_in[3];
    const float* thr   = (const float*)d_in[4];
    const float* dec   = (const float*)d_in[5];
    const int*   src   = (const int*)  d_in[6];
    const int*   dst   = (const int*)  d_in[7];
    float* out = (float*)d_out;

    const int THREADS = 256;
    int bn_blocks   = (B_DIM * N_DIM + THREADS - 1) / THREADS;
    int edge_blocks = (E_DIM * 4 + THREADS - 1) / THREADS;

    prep_kernel <<<bn_blocks,   THREADS>>>(chem, E, o_pre);
    edge_kernel <<<edge_blocks, THREADS>>>(w, src, dst);
    final_kernel<<<bn_blocks,   THREADS>>>(E, thr, dec, out);
}